// round 3
// baseline (speedup 1.0000x reference)
#include <cuda_runtime.h>

// Problem constants
#define Bdim 4
#define Cdim 16
#define Ldim 512
#define Hdim 1024

// Scratch: [2][B][L][C] floats, channel contiguous. 256 KB (fits L2 easily).
__device__ float g_scratch[2 * Bdim * Ldim * Cdim];

// ---------------------------------------------------------------------------
// Kernel A v3: per-row dot products, 4 rows per warp for max MLP.
// warp w in [0, 16384): tensor = w>>13, rows idx0 = (w & 8191)*4 .. +3.
// Rows never cross a (b,c) boundary (L=512 divisible by 4).
// __ldcs streaming on the 268 MB inputs keeps L2 free for scratch/output.
// ---------------------------------------------------------------------------
__global__ void __launch_bounds__(256) dot_kernel(
    const float* __restrict__ start,
    const float* __restrict__ end,
    const float* __restrict__ v)
{
    const unsigned warp = (blockIdx.x * blockDim.x + threadIdx.x) >> 5;
    const unsigned lane = threadIdx.x & 31;

    const unsigned tensor = warp >> 13;             // 0 or 1
    const unsigned idx0   = (warp & 8191) * 4;      // first of 4 rows

    const float* base = tensor ? end : start;
    const float4* row0 = (const float4*)(base + (size_t)idx0 * Hdim);
    const float4* v4   = (const float4*)(v + tensor * Hdim);
    const unsigned RS = Hdim / 4;                   // float4 row stride

    float s0 = 0.f, s1 = 0.f, s2 = 0.f, s3 = 0.f;
#pragma unroll
    for (int k = 0; k < Hdim / 4 / 32; k++) {       // 8 iterations
        const unsigned o = lane + 32 * k;
        float4 a0 = __ldcs(&row0[o]);
        float4 a1 = __ldcs(&row0[o + RS]);
        float4 a2 = __ldcs(&row0[o + 2 * RS]);
        float4 a3 = __ldcs(&row0[o + 3 * RS]);
        float4 w  = v4[o];
        s0 += a0.x * w.x + a0.y * w.y + a0.z * w.z + a0.w * w.w;
        s1 += a1.x * w.x + a1.y * w.y + a1.z * w.z + a1.w * w.w;
        s2 += a2.x * w.x + a2.y * w.y + a2.z * w.z + a2.w * w.w;
        s3 += a3.x * w.x + a3.y * w.y + a3.z * w.z + a3.w * w.w;
    }
#pragma unroll
    for (int o = 16; o; o >>= 1) {
        s0 += __shfl_xor_sync(0xFFFFFFFFu, s0, o);
        s1 += __shfl_xor_sync(0xFFFFFFFFu, s1, o);
        s2 += __shfl_xor_sync(0xFFFFFFFFu, s2, o);
        s3 += __shfl_xor_sync(0xFFFFFFFFu, s3, o);
    }

    if (lane == 0) {
        const unsigned b = idx0 >> 13;
        const unsigned c = (idx0 >> 9) & (Cdim - 1);
        const unsigned l = idx0 & (Ldim - 1);
        float* dst = &g_scratch[((tensor * Bdim + b) * Ldim + l) * Cdim + c];
        dst[0]        = s0;
        dst[Cdim]     = s1;
        dst[2 * Cdim] = s2;
        dst[3 * Cdim] = s3;
    }
}

// ---------------------------------------------------------------------------
// Kernel B v3: smem-tiled broadcast add, big tiles.
// Block covers (b, 16 i's, 128 j's, all 16 c) = 128 KB output, 256 threads.
// Smem: e tile 128x16 f (8 KB) + s tile 16x16 f (1 KB). 32 stores/thread.
// Thread t: q = t&3 (channel quarter), j0 = t>>2; handles j0 and j0+64.
// Warp stores are 512 B fully contiguous.
// ---------------------------------------------------------------------------
__global__ void __launch_bounds__(256) add_kernel(float4* __restrict__ out)
{
    __shared__ float4 e_sm[128 * 4];   // [j][q]
    __shared__ float4 s_sm[16 * 4];    // [i][q]

    const unsigned bx = blockIdx.x;
    const unsigned jt = bx & 3;            // j tile (128 j each)
    const unsigned it = (bx >> 2) & 31;    // i tile (16 i each)
    const unsigned b  = bx >> 7;

    const unsigned t = threadIdx.x;
    const float4* sc4 = (const float4*)g_scratch;   // [2][B][L][4] float4

    // cooperative loads: e tile = 512 float4 (2/thread), s tile = 64 float4
    {
        const float4* esrc = &sc4[((Bdim + b) * Ldim + jt * 128) * (Cdim / 4)];
        e_sm[t]       = esrc[t];
        e_sm[t + 256] = esrc[t + 256];
        if (t < 64)
            s_sm[t] = sc4[(b * Ldim + it * 16) * (Cdim / 4) + t];
    }
    __syncthreads();

    const unsigned q  = t & 3;
    const unsigned j0 = t >> 2;                     // 0..63
    const float4 e0 = e_sm[j0 * 4 + q];
    const float4 e1 = e_sm[(j0 + 64) * 4 + q];

    // out float4 index: ((b*L + I)*L + J)*4 + q
    float4* dst = &out[(((b * Ldim + it * 16) * Ldim) + jt * 128 + j0) * 4 + q];

#pragma unroll
    for (int i = 0; i < 16; i++) {
        float4 s = s_sm[i * 4 + q];
        float4* d = dst + (size_t)i * Ldim * 4;
        d[0]      = make_float4(s.x + e0.x, s.y + e0.y, s.z + e0.z, s.w + e0.w);
        d[64 * 4] = make_float4(s.x + e1.x, s.y + e1.y, s.z + e1.z, s.w + e1.w);
    }
}

extern "C" void kernel_launch(void* const* d_in, const int* in_sizes, int n_in,
                              void* d_out, int out_size)
{
    const float* start = (const float*)d_in[0];
    const float* end   = (const float*)d_in[1];
    const float* v     = (const float*)d_in[2];
    float4* out = (float4*)d_out;

    // Kernel A: 16384 warps (4 rows each) = 2048 blocks x 256 threads
    dot_kernel<<<2048, 256>>>(start, end, v);

    // Kernel B: 4 b x 32 i-tiles x 4 j-tiles = 512 blocks x 256 threads
    add_kernel<<<512, 256>>>(out);
}